// round 12
// baseline (speedup 1.0000x reference)
#include <cuda_runtime.h>
#include <cuda_bf16.h>
#include <math.h>
#include <stdint.h>

#define H 256
#define BM 64
#define MAXN 500000
#define MAXB 1024

// scratch (device globals: allocation-free rule)
__device__ float g_e[MAXN];           // exp(score) per node (shift-free)
__device__ float g_den[MAXB];         // softmax denominator per segment
__device__ int   g_seg[MAXB + 1];
__device__ int   g_is64;
// W1 prepacked for MMA B operand: [kt 0..15][tig 0..3][col 0..255] ->
// uint2 = ( bf16x2(rows kt*16+2tig, +1), bf16x2(rows kt*16+2tig+8, +9) )
__device__ uint2 g_Wpk2[16 * 1024];

// ---------------- helpers ----------------

__device__ __forceinline__ uint32_t bf2_pack(float a, float b) {
    __nv_bfloat162 h = __floats2bfloat162_rn(a, b);  // .x = a (low half)
    return *reinterpret_cast<uint32_t*>(&h);
}

__device__ __forceinline__ void mma_bf16(float c[4], const uint32_t a[4],
                                         uint32_t b0, uint32_t b1) {
    asm volatile(
        "mma.sync.aligned.m16n8k16.row.col.f32.bf16.bf16.f32 "
        "{%0,%1,%2,%3}, {%4,%5,%6,%7}, {%8,%9}, {%0,%1,%2,%3};\n"
        : "+f"(c[0]), "+f"(c[1]), "+f"(c[2]), "+f"(c[3])
        : "r"(a[0]), "r"(a[1]), "r"(a[2]), "r"(a[3]), "r"(b0), "r"(b1));
}

__device__ __forceinline__ float tanh_fast(float z) {
    float e = __expf(2.0f * z);
    return 1.0f - 2.0f / (e + 1.0f);
}

__device__ __forceinline__ void cp16(void* smem_dst, const void* gmem_src) {
    uint32_t s = (uint32_t)__cvta_generic_to_shared(smem_dst);
    asm volatile("cp.async.cg.shared.global [%0], [%1], 16;\n" :: "r"(s), "l"(gmem_src));
}
#define CP_COMMIT() asm volatile("cp.async.commit_group;\n" ::: "memory")
#define CP_WAIT(n)  asm volatile("cp.async.wait_group %0;\n" :: "n"(n) : "memory")

// ---------------- kernel 0: detect batch dtype (int32 vs int64) ----------------
__global__ void detect_kernel(const void* __restrict__ batch, int n, int B) {
    const long long* b64 = (const long long*)batch;
    int i0 = n / 2 - 1; if (i0 < 0) i0 = 0;
    int i1 = n / 4;     if (i1 >= n / 2) i1 = i0;
    long long v0 = b64[i0];
    long long v1 = b64[i1];
    g_is64 = (v0 >= 0 && v0 < B && v1 >= 0 && v1 < B) ? 1 : 0;
}

__device__ __forceinline__ int read_batch(const void* p, int i, int is64) {
    return is64 ? (int)((const long long*)p)[i] : ((const int*)p)[i];
}

// ---------------- kernel 0b: init denominators; prepack W1 ----------------
__global__ void init_kernel(int B) {
    int i = blockIdx.x * 256 + threadIdx.x;
    if (i < B) g_den[i] = 0.0f;
}

// blockIdx.x = kt*4 + tig (64 blocks), threadIdx.x = col (256)
__global__ void prep_kernel(const float* __restrict__ W1) {
    int kt  = blockIdx.x >> 2;
    int tig = blockIdx.x & 3;
    int col = threadIdx.x;
    int r0  = kt * 16 + 2 * tig;       // kpair tig
    int r1  = kt * 16 + 2 * tig + 8;   // kpair tig+4
    uint32_t lo = bf2_pack(W1[r0 * H + col], W1[(r0 + 1) * H + col]);
    uint32_t hi = bf2_pack(W1[r1 * H + col], W1[(r1 + 1) * H + col]);
    g_Wpk2[kt * 1024 + tig * 256 + col] = make_uint2(lo, hi);
}

// ---------------- kernel 1: segment boundaries ----------------
__global__ void seg_kernel(const void* __restrict__ batch, int n, int B) {
    int i = blockIdx.x * blockDim.x + threadIdx.x;
    if (i >= n) return;
    int is64 = g_is64;
    int b = read_batch(batch, i, is64);
    b = b < 0 ? 0 : (b >= B ? B - 1 : b);
    if (i == 0) {
        for (int bb = 0; bb <= b; ++bb) g_seg[bb] = 0;
    } else {
        int pb = read_batch(batch, i - 1, is64);
        pb = pb < 0 ? 0 : (pb >= B ? B - 1 : pb);
        if (pb != b)
            for (int bb = pb + 1; bb <= b; ++bb) g_seg[bb] = i;
    }
    if (i == n - 1) {
        for (int bb = b + 1; bb <= B; ++bb) g_seg[bb] = n;
    }
}

// ---------------- kernel 2: attention scores -> exp + denom ----------------
// s[i] = tanh(x[i,:] @ W1 + b1) @ W2  (b2 dropped: softmax shift-invariant)
// 1-term bf16 (X and W rounded): output rel err ~1e-5, threshold 1e-3.
// Triple-buffered W cp.async + 2-stage-ahead X prefetch: every load gets
// ~2 compute phases to land; wait_group 1 keeps one group in flight.
__global__ void __launch_bounds__(256, 2)
score_kernel(const float* __restrict__ x, const void* __restrict__ batch,
             const float* __restrict__ b1, const float* __restrict__ W2,
             int n) {
    __shared__ __align__(16) uint2    Wint[3][4 * 260];
    __shared__ __align__(16) uint32_t Xint[2][BM * 8];
    __shared__ float b1s[H];
    __shared__ float w2s[H];
    __shared__ float ssh[BM * 4];

    const int tid   = threadIdx.x;
    const int lane  = tid & 31;
    const int warp  = tid >> 5;
    const int warpM = warp >> 2;   // 0..1
    const int warpN = warp & 3;    // 0..3
    const int gid   = lane >> 2;   // 0..7
    const int tig   = lane & 3;    // 0..3
    const long long m0 = (long long)blockIdx.x * BM;

    b1s[tid] = b1[tid];
    w2s[tid] = W2[tid];

    const int xr = tid >> 2;     // 0..63
    const int xc = tid & 3;      // 0..3
    const bool xok = (m0 + xr < n);
    const float* xrow = x + (m0 + xr) * (long long)H;

    // pair p -> word slot
    const int p0 = 2 * xc, p1 = 2 * xc + 1;
    const int ws0 = (p0 < 4) ? 2 * p0 : 2 * (p0 - 4) + 1;
    const int ws1 = (p1 < 4) ? 2 * p1 : 2 * (p1 - 4) + 1;
    const int xbase = xr * 8;

    // W stage: 8KB -> 512 x 16B chunks -> 2 per thread.
    #define CP_W_STAGE(kt, buf)                                              \
        _Pragma("unroll")                                                    \
        for (int k_ = 0; k_ < 2; ++k_) {                                     \
            int c_ = tid + k_ * 256;                                         \
            int pi_ = c_ >> 7;                                               \
            int cp_ = c_ & 127;                                              \
            cp16(&Wint[buf][pi_ * 260 + cp_ * 2],                            \
                 (const char*)g_Wpk2 + (kt) * 8192 + c_ * 16);               \
        }

    #define PACK_X(buf, v)                                                   \
        {                                                                    \
            Xint[buf][xbase + ws0] = bf2_pack((v).x, (v).y);                 \
            Xint[buf][xbase + ws1] = bf2_pack((v).z, (v).w);                 \
        }

    // prologue: W0, W1 in flight; X0 packed; X1 slice loading
    CP_W_STAGE(0, 0); CP_COMMIT();
    CP_W_STAGE(1, 1); CP_COMMIT();
    float4 xv = make_float4(0.f, 0.f, 0.f, 0.f);
    if (xok) xv = *(const float4*)(xrow + xc * 4);
    PACK_X(0, xv);
    float4 xvA = make_float4(0.f, 0.f, 0.f, 0.f);
    if (xok) xvA = *(const float4*)(xrow + 16 + xc * 4);
    CP_WAIT(1);          // W0 landed (W1 may fly)
    __syncthreads();

    float acc[2][8][4];
    #pragma unroll
    for (int mt = 0; mt < 2; ++mt)
        #pragma unroll
        for (int nt = 0; nt < 8; ++nt)
            #pragma unroll
            for (int c = 0; c < 4; ++c) acc[mt][nt][c] = 0.0f;

    #pragma unroll
    for (int kt = 0; kt < 16; ++kt) {
        const int wb = kt % 3;
        const int xb = kt & 1;

        // issue stage kt+2 loads (2 phases of cover)
        float4 xvB = make_float4(0.f, 0.f, 0.f, 0.f);
        if (kt < 14) {
            CP_W_STAGE(kt + 2, (kt + 2) % 3);
            CP_COMMIT();
            if (xok) xvB = *(const float4*)(xrow + (kt + 2) * 16 + xc * 4);
        }

        // compute stage kt
        uint32_t ah[2][4];
        #pragma unroll
        for (int mt = 0; mt < 2; ++mt) {
            int r0 = warpM * 32 + mt * 16 + gid;
            uint2 qa = *(const uint2*)&Xint[xb][r0 * 8 + 2 * tig];
            uint2 qb = *(const uint2*)&Xint[xb][(r0 + 8) * 8 + 2 * tig];
            ah[mt][0] = qa.x; ah[mt][2] = qa.y;
            ah[mt][1] = qb.x; ah[mt][3] = qb.y;
        }
        #pragma unroll
        for (int nt = 0; nt < 8; ++nt) {
            int cB = warpN * 64 + nt * 8 + gid;
            uint2 bp = Wint[wb][tig * 260 + cB];   // (kpair tig, kpair tig+4)
            mma_bf16(acc[0][nt], ah[0], bp.x, bp.y);
            mma_bf16(acc[1][nt], ah[1], bp.x, bp.y);
        }

        if (kt < 15) {
            if (kt < 14) { CP_WAIT(1); }   // W[kt+1] landed, W[kt+2] may fly
            else         { CP_WAIT(0); }   // final W15 landed
            PACK_X(xb ^ 1, xvA);           // X slice kt+1 (loaded at kt-1)
            xvA = xvB;
        }
        __syncthreads();   // stage consumed; stage kt+1 W/X visible
    }

    // epilogue: s_row = sum_cols tanh(z + b1) * w2
    #pragma unroll
    for (int mt = 0; mt < 2; ++mt) {
        float p0v = 0.0f, p1v = 0.0f;
        #pragma unroll
        for (int nt = 0; nt < 8; ++nt) {
            int c0 = warpN * 64 + nt * 8 + 2 * tig;
            float w0 = w2s[c0], w1v = w2s[c0 + 1];
            float e0 = b1s[c0], e1 = b1s[c0 + 1];
            p0v += w0 * tanh_fast(acc[mt][nt][0] + e0) + w1v * tanh_fast(acc[mt][nt][1] + e1);
            p1v += w0 * tanh_fast(acc[mt][nt][2] + e0) + w1v * tanh_fast(acc[mt][nt][3] + e1);
        }
        p0v += __shfl_xor_sync(0xffffffffu, p0v, 1);
        p0v += __shfl_xor_sync(0xffffffffu, p0v, 2);
        p1v += __shfl_xor_sync(0xffffffffu, p1v, 1);
        p1v += __shfl_xor_sync(0xffffffffu, p1v, 2);
        if (tig == 0) {
            int row0 = warpM * 32 + mt * 16 + gid;
            ssh[row0 * 4 + warpN]       = p0v;
            ssh[(row0 + 8) * 4 + warpN] = p1v;
        }
    }
    __syncthreads();
    if (tid < BM && m0 + tid < n) {
        float s = ssh[tid * 4] + ssh[tid * 4 + 1] + ssh[tid * 4 + 2] + ssh[tid * 4 + 3];
        float e = __expf(s);
        g_e[m0 + tid] = e;
        int b = read_batch(batch, (int)(m0 + tid), g_is64);
        atomicAdd(&g_den[b], e);
    }
}

// ---------------- kernel 3: fused mean/max/attn pooling ----------------
__global__ void pool_kernel(const float* __restrict__ x, float* __restrict__ out, int B) {
    int b = blockIdx.x;
    int start = g_seg[b], end = g_seg[b + 1];
    int len = end - start;
    float* orow = out + (long long)b * (3 * H);

    if (len <= 0) {
        for (int j = threadIdx.x; j < 3 * H; j += 256) orow[j] = 0.0f;
        return;
    }

    int r = threadIdx.x >> 6;   // 0..3
    int c = threadIdx.x & 63;   // 0..63 (float4 col)

    float4 sum = make_float4(0.f, 0.f, 0.f, 0.f);
    float4 att = make_float4(0.f, 0.f, 0.f, 0.f);
    float4 mx  = make_float4(-INFINITY, -INFINITY, -INFINITY, -INFINITY);

    for (int i = start + r; i < end; i += 4) {
        float ei = g_e[i];
        float4 xv = *(const float4*)(x + (long long)i * H + c * 4);
        sum.x += xv.x; sum.y += xv.y; sum.z += xv.z; sum.w += xv.w;
        mx.x = fmaxf(mx.x, xv.x); mx.y = fmaxf(mx.y, xv.y);
        mx.z = fmaxf(mx.z, xv.z); mx.w = fmaxf(mx.w, xv.w);
        att.x += ei * xv.x; att.y += ei * xv.y;
        att.z += ei * xv.z; att.w += ei * xv.w;
    }

    __shared__ float4 shsum[4][64];
    __shared__ float4 shmax[4][64];
    __shared__ float4 shatt[4][64];
    shsum[r][c] = sum; shmax[r][c] = mx; shatt[r][c] = att;
    __syncthreads();

    if (r == 0) {
        #pragma unroll
        for (int rr = 1; rr < 4; ++rr) {
            float4 s2 = shsum[rr][c], m2 = shmax[rr][c], a2 = shatt[rr][c];
            sum.x += s2.x; sum.y += s2.y; sum.z += s2.z; sum.w += s2.w;
            mx.x = fmaxf(mx.x, m2.x); mx.y = fmaxf(mx.y, m2.y);
            mx.z = fmaxf(mx.z, m2.z); mx.w = fmaxf(mx.w, m2.w);
            att.x += a2.x; att.y += a2.y; att.z += a2.z; att.w += a2.w;
        }
        float invc = 1.0f / (float)len;
        float invd = 1.0f / g_den[b];
        float4 mean = make_float4(sum.x * invc, sum.y * invc, sum.z * invc, sum.w * invc);
        float4 attn = make_float4(att.x * invd, att.y * invd, att.z * invd, att.w * invd);
        *(float4*)(orow + c * 4)         = mean;
        *(float4*)(orow + H + c * 4)     = mx;
        *(float4*)(orow + 2 * H + c * 4) = attn;
    }
}

// ---------------- launch (score at ncu index 3) ----------------
extern "C" void kernel_launch(void* const* d_in, const int* in_sizes, int n_in,
                              void* d_out, int out_size) {
    const float* x     = (const float*)d_in[0];
    const void*  batch = d_in[1];
    const float* W1    = (const float*)d_in[2];
    const float* b1    = (const float*)d_in[3];
    const float* W2    = (const float*)d_in[4];
    float*       out   = (float*)d_out;

    int n = in_sizes[1];
    int B = out_size / (3 * H);

    detect_kernel<<<1, 1>>>(batch, n, B);
    prep_kernel<<<64, 256>>>(W1);
    init_kernel<<<(B + 255) / 256, 256>>>(B);
    score_kernel<<<(n + BM - 1) / BM, 256>>>(x, batch, b1, W2, n);
    seg_kernel<<<(n + 255) / 256, 256>>>(batch, n, B);
    pool_kernel<<<B, 256>>>(x, out, B);
}

// round 13
// speedup vs baseline: 1.0372x; 1.0372x over previous
#include <cuda_runtime.h>
#include <cuda_bf16.h>
#include <math.h>
#include <stdint.h>

#define H 256
#define BM 64
#define MAXN 500000
#define MAXB 1024

// scratch (device globals: allocation-free rule)
__device__ float g_e[MAXN];           // exp(score) per node (shift-free)
__device__ float g_den[MAXB];         // softmax denominator per segment
__device__ int   g_seg[MAXB + 1];
__device__ int   g_is64;
// W1 prepacked for MMA B operand: [kt 0..15][tig 0..3][col 0..255] ->
// uint2 = ( bf16x2(rows kt*16+2tig, +1), bf16x2(rows kt*16+2tig+8, +9) )
__device__ uint2 g_Wpk2[16 * 1024];

// ---------------- helpers ----------------

__device__ __forceinline__ uint32_t bf2_pack(float a, float b) {
    __nv_bfloat162 h = __floats2bfloat162_rn(a, b);  // .x = a (low half)
    return *reinterpret_cast<uint32_t*>(&h);
}

__device__ __forceinline__ void mma_bf16(float c[4], const uint32_t a[4],
                                         uint32_t b0, uint32_t b1) {
    asm volatile(
        "mma.sync.aligned.m16n8k16.row.col.f32.bf16.bf16.f32 "
        "{%0,%1,%2,%3}, {%4,%5,%6,%7}, {%8,%9}, {%0,%1,%2,%3};\n"
        : "+f"(c[0]), "+f"(c[1]), "+f"(c[2]), "+f"(c[3])
        : "r"(a[0]), "r"(a[1]), "r"(a[2]), "r"(a[3]), "r"(b0), "r"(b1));
}

__device__ __forceinline__ float tanh_fast(float z) {
    float e = __expf(2.0f * z);
    return 1.0f - 2.0f / (e + 1.0f);
}

__device__ __forceinline__ void cp16(void* smem_dst, const void* gmem_src) {
    uint32_t s = (uint32_t)__cvta_generic_to_shared(smem_dst);
    asm volatile("cp.async.cg.shared.global [%0], [%1], 16;\n" :: "r"(s), "l"(gmem_src));
}
#define CP_COMMIT() asm volatile("cp.async.commit_group;\n" ::: "memory")
#define CP_WAIT(n)  asm volatile("cp.async.wait_group %0;\n" :: "n"(n) : "memory")

// ---------------- kernel 0: detect batch dtype (int32 vs int64) ----------------
__global__ void detect_kernel(const void* __restrict__ batch, int n, int B) {
    const long long* b64 = (const long long*)batch;
    int i0 = n / 2 - 1; if (i0 < 0) i0 = 0;
    int i1 = n / 4;     if (i1 >= n / 2) i1 = i0;
    long long v0 = b64[i0];
    long long v1 = b64[i1];
    g_is64 = (v0 >= 0 && v0 < B && v1 >= 0 && v1 < B) ? 1 : 0;
}

__device__ __forceinline__ int read_batch(const void* p, int i, int is64) {
    return is64 ? (int)((const long long*)p)[i] : ((const int*)p)[i];
}

// ---------------- kernel 0b: init denominators; prepack W1 ----------------
__global__ void init_kernel(int B) {
    int i = blockIdx.x * 256 + threadIdx.x;
    if (i < B) g_den[i] = 0.0f;
}

// blockIdx.x = kt*4 + tig (64 blocks), threadIdx.x = col (256)
__global__ void prep_kernel(const float* __restrict__ W1) {
    int kt  = blockIdx.x >> 2;
    int tig = blockIdx.x & 3;
    int col = threadIdx.x;
    int r0  = kt * 16 + 2 * tig;       // kpair tig
    int r1  = kt * 16 + 2 * tig + 8;   // kpair tig+4
    uint32_t lo = bf2_pack(W1[r0 * H + col], W1[(r0 + 1) * H + col]);
    uint32_t hi = bf2_pack(W1[r1 * H + col], W1[(r1 + 1) * H + col]);
    g_Wpk2[kt * 1024 + tig * 256 + col] = make_uint2(lo, hi);
}

// ---------------- kernel 1: segment boundaries ----------------
__global__ void seg_kernel(const void* __restrict__ batch, int n, int B) {
    int i = blockIdx.x * blockDim.x + threadIdx.x;
    if (i >= n) return;
    int is64 = g_is64;
    int b = read_batch(batch, i, is64);
    b = b < 0 ? 0 : (b >= B ? B - 1 : b);
    if (i == 0) {
        for (int bb = 0; bb <= b; ++bb) g_seg[bb] = 0;
    } else {
        int pb = read_batch(batch, i - 1, is64);
        pb = pb < 0 ? 0 : (pb >= B ? B - 1 : pb);
        if (pb != b)
            for (int bb = pb + 1; bb <= b; ++bb) g_seg[bb] = i;
    }
    if (i == n - 1) {
        for (int bb = b + 1; bb <= B; ++bb) g_seg[bb] = n;
    }
}

// ---------------- kernel 2: attention scores -> exp + denom ----------------
// s[i] = tanh(x[i,:] @ W1 + b1) @ W2  (b2 dropped: softmax shift-invariant)
// 1-term bf16 (X and W rounded): output rel err ~1e-5, threshold 1e-3.
// K=32 per stage, 8 stages: 32 MMAs/warp between barriers (2x issue runs,
// half the sync points vs K=16). W double-buffered cp.async; X 1-ahead LDG.
// X smem [row][24 words]: pairs of k16-block b at words b*8 + slot(w),
//   slot(w) = (w<4 ? 2w : 2(w-4)+1); A read = uint2 at row*24+b*8+2tig.
//   Banks per phase: 24*gid+2tig mod 32 = {0,24,16,8}+{0,2,4,6} distinct.
// W smem uint2 [ktl][4*260]: read banks 8tig+2gid+{0,16} distinct.
__global__ void __launch_bounds__(256, 2)
score_kernel(const float* __restrict__ x, const void* __restrict__ batch,
             const float* __restrict__ b1, const float* __restrict__ W2,
             int n) {
    __shared__ __align__(16) uint2    Wint[2][2][4 * 260];
    __shared__ __align__(16) uint32_t Xint[2][BM * 24];
    __shared__ float b1s[H];
    __shared__ float w2s[H];
    __shared__ float ssh[BM * 4];

    const int tid   = threadIdx.x;
    const int lane  = tid & 31;
    const int warp  = tid >> 5;
    const int warpM = warp >> 2;   // 0..1
    const int warpN = warp & 3;    // 0..3
    const int gid   = lane >> 2;   // 0..7
    const int tig   = lane & 3;    // 0..3
    const long long m0 = (long long)blockIdx.x * BM;

    b1s[tid] = b1[tid];
    w2s[tid] = W2[tid];

    const int xr = tid >> 2;     // 0..63
    const int xc = tid & 3;      // 0..3
    const bool xok = (m0 + xr < n);
    const float* xrow = x + (m0 + xr) * (long long)H;

    // slot base for float4 chunk (c & 3 = xc): {0,4,1,5}
    const int s0tab[4] = {0, 4, 1, 5};
    const int s0 = s0tab[xc];
    const int xbase = xr * 24;

    // W stage (16KB = two g_Wpk2 entries): 1024 x 16B chunks -> 4 per thread.
    // chunk c: ktl = c>>9, cc = c&511, pi = cc>>7, cp = cc&127.
    #define CP_W_STAGE(s_, buf)                                              \
        _Pragma("unroll")                                                    \
        for (int k_ = 0; k_ < 4; ++k_) {                                     \
            int c_  = tid + k_ * 256;                                        \
            int kl_ = c_ >> 9;                                               \
            int cc_ = c_ & 511;                                              \
            int pi_ = cc_ >> 7;                                              \
            int cp_ = cc_ & 127;                                             \
            cp16(&Wint[buf][kl_][pi_ * 260 + cp_ * 2],                       \
                 (const char*)g_Wpk2 + (s_) * 16384 + c_ * 16);              \
        }

    // pack one stage's X slice: chunks xc (block 0) and xc+4 (block 1)
    #define PACK_X(buf, va, vb)                                              \
        {                                                                    \
            Xint[buf][xbase + s0]          = bf2_pack((va).x, (va).y);       \
            Xint[buf][xbase + s0 + 2]      = bf2_pack((va).z, (va).w);       \
            Xint[buf][xbase + 8 + s0]      = bf2_pack((vb).x, (vb).y);       \
            Xint[buf][xbase + 8 + s0 + 2]  = bf2_pack((vb).z, (vb).w);       \
        }

    #define LOAD_XF(s_, va, vb)                                              \
        {                                                                    \
            (va) = make_float4(0.f, 0.f, 0.f, 0.f);                          \
            (vb) = make_float4(0.f, 0.f, 0.f, 0.f);                          \
            if (xok) {                                                       \
                (va) = *(const float4*)(xrow + (s_) * 32 + xc * 4);          \
                (vb) = *(const float4*)(xrow + (s_) * 32 + 16 + xc * 4);     \
            }                                                                \
        }

    // prologue: stage 0
    CP_W_STAGE(0, 0);
    CP_COMMIT();
    float4 xa, xb;
    LOAD_XF(0, xa, xb);
    PACK_X(0, xa, xb);
    CP_WAIT(0);
    __syncthreads();

    float acc[2][8][4];
    #pragma unroll
    for (int mt = 0; mt < 2; ++mt)
        #pragma unroll
        for (int nt = 0; nt < 8; ++nt)
            #pragma unroll
            for (int c = 0; c < 4; ++c) acc[mt][nt][c] = 0.0f;

    #pragma unroll
    for (int s = 0; s < 8; ++s) {
        const int cur = s & 1;
        const int nxt = cur ^ 1;

        float4 xan, xbn;
        if (s < 7) {
            CP_W_STAGE(s + 1, nxt);
            CP_COMMIT();
            LOAD_XF(s + 1, xan, xbn);
        }

        // compute stage s: two k16 blocks, 32 MMAs
        #pragma unroll
        for (int kl = 0; kl < 2; ++kl) {
            uint32_t ah[2][4];
            #pragma unroll
            for (int mt = 0; mt < 2; ++mt) {
                int r0 = warpM * 32 + mt * 16 + gid;
                uint2 qa = *(const uint2*)&Xint[cur][r0 * 24 + kl * 8 + 2 * tig];
                uint2 qb = *(const uint2*)&Xint[cur][(r0 + 8) * 24 + kl * 8 + 2 * tig];
                ah[mt][0] = qa.x; ah[mt][2] = qa.y;
                ah[mt][1] = qb.x; ah[mt][3] = qb.y;
            }
            #pragma unroll
            for (int nt = 0; nt < 8; ++nt) {
                int cB = warpN * 64 + nt * 8 + gid;
                uint2 bp = Wint[cur][kl][tig * 260 + cB];
                mma_bf16(acc[0][nt], ah[0], bp.x, bp.y);
                mma_bf16(acc[1][nt], ah[1], bp.x, bp.y);
            }
        }

        if (s < 7) {
            CP_WAIT(0);            // W[s+1] landed (covered by 32-MMA compute)
            PACK_X(nxt, xan, xbn);
        }
        __syncthreads();           // stage consumed; next stage visible
    }

    // epilogue: s_row = sum_cols tanh(z + b1) * w2
    #pragma unroll
    for (int mt = 0; mt < 2; ++mt) {
        float p0v = 0.0f, p1v = 0.0f;
        #pragma unroll
        for (int nt = 0; nt < 8; ++nt) {
            int c0 = warpN * 64 + nt * 8 + 2 * tig;
            float w0 = w2s[c0], w1v = w2s[c0 + 1];
            float e0 = b1s[c0], e1 = b1s[c0 + 1];
            p0v += w0 * tanh_fast(acc[mt][nt][0] + e0) + w1v * tanh_fast(acc[mt][nt][1] + e1);
            p1v += w0 * tanh_fast(acc[mt][nt][2] + e0) + w1v * tanh_fast(acc[mt][nt][3] + e1);
        }
        p0v += __shfl_xor_sync(0xffffffffu, p0v, 1);
        p0v += __shfl_xor_sync(0xffffffffu, p0v, 2);
        p1v += __shfl_xor_sync(0xffffffffu, p1v, 1);
        p1v += __shfl_xor_sync(0xffffffffu, p1v, 2);
        if (tig == 0) {
            int row0 = warpM * 32 + mt * 16 + gid;
            ssh[row0 * 4 + warpN]       = p0v;
            ssh[(row0 + 8) * 4 + warpN] = p1v;
        }
    }
    __syncthreads();
    if (tid < BM && m0 + tid < n) {
        float s = ssh[tid * 4] + ssh[tid * 4 + 1] + ssh[tid * 4 + 2] + ssh[tid * 4 + 3];
        float e = __expf(s);
        g_e[m0 + tid] = e;
        int b = read_batch(batch, (int)(m0 + tid), g_is64);
        atomicAdd(&g_den[b], e);
    }
}

// ---------------- kernel 3: fused mean/max/attn pooling ----------------
__global__ void pool_kernel(const float* __restrict__ x, float* __restrict__ out, int B) {
    int b = blockIdx.x;
    int start = g_seg[b], end = g_seg[b + 1];
    int len = end - start;
    float* orow = out + (long long)b * (3 * H);

    if (len <= 0) {
        for (int j = threadIdx.x; j < 3 * H; j += 256) orow[j] = 0.0f;
        return;
    }

    int r = threadIdx.x >> 6;   // 0..3
    int c = threadIdx.x & 63;   // 0..63 (float4 col)

    float4 sum = make_float4(0.f, 0.f, 0.f, 0.f);
    float4 att = make_float4(0.f, 0.f, 0.f, 0.f);
    float4 mx  = make_float4(-INFINITY, -INFINITY, -INFINITY, -INFINITY);

    for (int i = start + r; i < end; i += 4) {
        float ei = g_e[i];
        float4 xv = *(const float4*)(x + (long long)i * H + c * 4);
        sum.x += xv.x; sum.y += xv.y; sum.z += xv.z; sum.w += xv.w;
        mx.x = fmaxf(mx.x, xv.x); mx.y = fmaxf(mx.y, xv.y);
        mx.z = fmaxf(mx.z, xv.z); mx.w = fmaxf(mx.w, xv.w);
        att.x += ei * xv.x; att.y += ei * xv.y;
        att.z += ei * xv.z; att.w += ei * xv.w;
    }

    __shared__ float4 shsum[4][64];
    __shared__ float4 shmax[4][64];
    __shared__ float4 shatt[4][64];
    shsum[r][c] = sum; shmax[r][c] = mx; shatt[r][c] = att;
    __syncthreads();

    if (r == 0) {
        #pragma unroll
        for (int rr = 1; rr < 4; ++rr) {
            float4 s2 = shsum[rr][c], m2 = shmax[rr][c], a2 = shatt[rr][c];
            sum.x += s2.x; sum.y += s2.y; sum.z += s2.z; sum.w += s2.w;
            mx.x = fmaxf(mx.x, m2.x); mx.y = fmaxf(mx.y, m2.y);
            mx.z = fmaxf(mx.z, m2.z); mx.w = fmaxf(mx.w, m2.w);
            att.x += a2.x; att.y += a2.y; att.z += a2.z; att.w += a2.w;
        }
        float invc = 1.0f / (float)len;
        float invd = 1.0f / g_den[b];
        float4 mean = make_float4(sum.x * invc, sum.y * invc, sum.z * invc, sum.w * invc);
        float4 attn = make_float4(att.x * invd, att.y * invd, att.z * invd, att.w * invd);
        *(float4*)(orow + c * 4)         = mean;
        *(float4*)(orow + H + c * 4)     = mx;
        *(float4*)(orow + 2 * H + c * 4) = attn;
    }
}

// ---------------- launch (score at ncu index 3) ----------------
extern "C" void kernel_launch(void* const* d_in, const int* in_sizes, int n_in,
                              void* d_out, int out_size) {
    const float* x     = (const float*)d_in[0];
    const void*  batch = d_in[1];
    const float* W1    = (const float*)d_in[2];
    const float* b1    = (const float*)d_in[3];
    const float* W2    = (const float*)d_in[4];
    float*       out   = (float*)d_out;

    int n = in_sizes[1];
    int B = out_size / (3 * H);

    detect_kernel<<<1, 1>>>(batch, n, B);
    prep_kernel<<<64, 256>>>(W1);
    init_kernel<<<(B + 255) / 256, 256>>>(B);
    score_kernel<<<(n + BM - 1) / BM, 256>>>(x, batch, b1, W2, n);
    seg_kernel<<<(n + 255) / 256, 256>>>(batch, n, B);
    pool_kernel<<<B, 256>>>(x, out, B);
}